// round 13
// baseline (speedup 1.0000x reference)
#include <cuda_runtime.h>

#define LATENTS 128
#define HIDDEN  256
#define TM      32
#define NTHR    1024
#define TSTEPS  100
#define NROWS   4096

typedef unsigned long long ULL;

__device__ __forceinline__ ULL ffma2(ULL a, ULL b, ULL c) {
    ULL d; asm("fma.rn.f32x2 %0, %1, %2, %3;" : "=l"(d) : "l"(a), "l"(b), "l"(c)); return d;
}
__device__ __forceinline__ ULL pack2(float x) {
    ULL d; asm("mov.b64 %0, {%1, %1};" : "=l"(d) : "f"(x)); return d;
}
__device__ __forceinline__ ULL packab(float a, float b) {
    ULL d; asm("mov.b64 %0, {%1, %2};" : "=l"(d) : "f"(a), "f"(b)); return d;
}
__device__ __forceinline__ void unpack2(ULL v, float& lo, float& hi) {
    asm("mov.b64 {%0, %1}, %2;" : "=f"(lo), "=f"(hi) : "l"(v));
}
__device__ __forceinline__ float fast_tanh(float x) {
    float e = __expf(2.0f * x);
    return 1.0f - __fdividef(2.0f, e + 1.0f);
}

// smem (bytes): W1s [0,131072)       fp32[128][256]
//               Yp  [131072,147456)  ULL [16][128]   row-pair state
//               Zp  [147456,180224)  ULL [16][256]   row-pair tanh acts
//               Red [180224,196608)  16KB partner-reduction buffer
#define SM_BYTES 196608

__global__ __launch_bounds__(NTHR, 1)
void ode_rk4_kernel(const float* __restrict__ fp,
                    const float* __restrict__ ts,
                    const float* __restrict__ W1,
                    const float* __restrict__ b1,
                    const float* __restrict__ W2,
                    const float* __restrict__ b2,
                    float* __restrict__ out)
{
    extern __shared__ char smraw[];
    float* W1s = (float*)smraw;
    ULL*   Yp  = (ULL*)(smraw + 131072);
    ULL*   Zp  = (ULL*)(smraw + 147456);
    ULL*   Red = (ULL*)(smraw + 180224);

    const int tid = threadIdx.x;
    const int tc  = tid & 31;
    const int w   = tid >> 5;            // 0..31
    // GEMM1: pairs {2wr, 2wr+1}, cols (c1, c1+1)
    const int wr  = w >> 2;              // 0..7
    const int wc  = w & 3;
    const int c1  = 64 * wc + 2 * tc;
    // GEMM2/epi: pairs {2rga, 2rga+1}, cols (cb, cb+1), k-half gr
    const int rga = (w & 15) >> 1;       // 0..7
    const int wc2 = w & 1;
    const int cb  = 64 * wc2 + 2 * tc;
    const int gr  = w >> 4;              // 0..1 -> ks [128gr, 128gr+128)
    const bool epi_w = (w < 16);
    const int row0 = blockIdx.x * TM;

    // Stage W1 (coalesced float4).
    for (int i = tid; i < LATENTS * HIDDEN / 4; i += NTHR)
        ((float4*)W1s)[i] = ((const float4*)W1)[i];

    // t=0 output, fully coalesced.
    for (int i = tid; i < TM * LATENTS / 4; i += NTHR) {
        int r = i >> 5, c4 = i & 31;
        float4 v = ((const float4*)(fp + (size_t)(row0 + r) * LATENTS))[c4];
        ((float4*)(out + (size_t)(row0 + r) * TSTEPS * LATENTS))[c4] = v;
    }

    const ULL rb1lo = pack2(b1[c1]);
    const ULL rb1hi = pack2(b1[c1 + 1]);

    ULL yb[2][2], acc[2][2], rb2[2];
    rb2[0] = pack2(b2[cb]);
    rb2[1] = pack2(b2[cb + 1]);
    if (epi_w) {
        #pragma unroll
        for (int p = 0; p < 2; p++) {
            int r = row0 + 4 * rga + 2 * p;
            yb[p][0] = packab(fp[(size_t)r * LATENTS + cb],     fp[(size_t)(r + 1) * LATENTS + cb]);
            yb[p][1] = packab(fp[(size_t)r * LATENTS + cb + 1], fp[(size_t)(r + 1) * LATENTS + cb + 1]);
            ulonglong2 yy; yy.x = yb[p][0]; yy.y = yb[p][1];
            *(ulonglong2*)&Yp[(2 * rga + p) * LATENTS + cb] = yy;
        }
    }
    __syncthreads();

    for (int t = 0; t < TSTEPS - 1; t++) {
        float dt   = __ldg(&ts[t + 1]) - __ldg(&ts[t]);
        float half = 0.5f * dt;

        #pragma unroll 1
        for (int s = 0; s < 4; s++) {
            // ---------------- GEMM1 (all 32 warps, 2 row-pairs each) --------
            ULL h[2][2];
            #pragma unroll
            for (int p = 0; p < 2; p++) { h[p][0] = rb1lo; h[p][1] = rb1hi; }
            {
                const float* w1c = &W1s[c1];
                const ULL*   yp0 = &Yp[(2 * wr + 0) * LATENTS];
                const ULL*   yp1 = &Yp[(2 * wr + 1) * LATENTS];
                #pragma unroll 4
                for (int k0 = 0; k0 < LATENTS; k0 += 2) {
                    ulonglong2 a0 = *(const ulonglong2*)&yp0[k0];
                    ulonglong2 a1 = *(const ulonglong2*)&yp1[k0];
                    ULL wv0 = *(const ULL*)&w1c[(k0    ) * HIDDEN];
                    ULL wv1 = *(const ULL*)&w1c[(k0 + 1) * HIDDEN];
                    float wl, wh;
                    unpack2(wv0, wl, wh);
                    { ULL bl = pack2(wl), bh = pack2(wh);
                      h[0][0] = ffma2(a0.x, bl, h[0][0]); h[0][1] = ffma2(a0.x, bh, h[0][1]);
                      h[1][0] = ffma2(a1.x, bl, h[1][0]); h[1][1] = ffma2(a1.x, bh, h[1][1]); }
                    unpack2(wv1, wl, wh);
                    { ULL bl = pack2(wl), bh = pack2(wh);
                      h[0][0] = ffma2(a0.y, bl, h[0][0]); h[0][1] = ffma2(a0.y, bh, h[0][1]);
                      h[1][0] = ffma2(a1.y, bl, h[1][0]); h[1][1] = ffma2(a1.y, bh, h[1][1]); }
                }
            }

            // tanh -> Zp (dense STS.128, conflict-free).
            #pragma unroll
            for (int p = 0; p < 2; p++) {
                float x0, x1, x2, x3;
                unpack2(h[p][0], x0, x1);
                unpack2(h[p][1], x2, x3);
                ulonglong2 zz;
                zz.x = packab(fast_tanh(x0), fast_tanh(x1));
                zz.y = packab(fast_tanh(x2), fast_tanh(x3));
                *(ulonglong2*)&Zp[(2 * wr + p) * HIDDEN + c1] = zz;
            }
            __syncthreads();

            // ------- GEMM2: 32 warps; W2 streamed via LDG (L1/L2-resident) --
            ULL o[2][2];
            if (gr == 0) {
                o[0][0] = rb2[0]; o[0][1] = rb2[1];
                o[1][0] = rb2[0]; o[1][1] = rb2[1];
            } else {
                o[0][0] = 0ULL; o[0][1] = 0ULL;
                o[1][0] = 0ULL; o[1][1] = 0ULL;
            }

            {
                const ULL* zb0 = &Zp[(2 * rga + 0) * HIDDEN + 128 * gr];
                const ULL* zb1 = &Zp[(2 * rga + 1) * HIDDEN + 128 * gr];
                const float* Wg = W2 + (size_t)(128 * gr) * LATENTS + cb;

                ULL wbuf[2][8];
                #pragma unroll
                for (int q = 0; q < 8; q++)
                    wbuf[0][q] = *(const ULL*)&Wg[q * LATENTS];

                #pragma unroll 1
                for (int c = 0; c < 16; c++) {
                    if (c < 15) {
                        #pragma unroll
                        for (int q = 0; q < 8; q++)
                            wbuf[(c + 1) & 1][q] = *(const ULL*)&Wg[(8 * (c + 1) + q) * LATENTS];
                    }
                    #pragma unroll
                    for (int q = 0; q < 8; q += 2) {
                        const int kk = 8 * c + q;
                        ulonglong2 a0 = *(const ulonglong2*)&zb0[kk];
                        ulonglong2 a1 = *(const ulonglong2*)&zb1[kk];
                        ULL wv0 = wbuf[c & 1][q];
                        ULL wv1 = wbuf[c & 1][q + 1];
                        float wl, wh;
                        unpack2(wv0, wl, wh);
                        { ULL bl = pack2(wl), bh = pack2(wh);
                          o[0][0] = ffma2(a0.x, bl, o[0][0]); o[0][1] = ffma2(a0.x, bh, o[0][1]);
                          o[1][0] = ffma2(a1.x, bl, o[1][0]); o[1][1] = ffma2(a1.x, bh, o[1][1]); }
                        unpack2(wv1, wl, wh);
                        { ULL bl = pack2(wl), bh = pack2(wh);
                          o[0][0] = ffma2(a0.y, bl, o[0][0]); o[0][1] = ffma2(a0.y, bh, o[0][1]);
                          o[1][0] = ffma2(a1.y, bl, o[1][0]); o[1][1] = ffma2(a1.y, bh, o[1][1]); }
                    }
                }
            }

            // ------- partner reduction: gr=1 -> Red, gr=0 adds --------------
            if (gr == 1) {
                ULL* rd = &Red[((w - 16) * 32 + tc) * 4];
                ulonglong2 v0; v0.x = o[0][0]; v0.y = o[0][1];
                ulonglong2 v1; v1.x = o[1][0]; v1.y = o[1][1];
                *(ulonglong2*)&rd[0] = v0;
                *(ulonglong2*)&rd[2] = v1;
            }
            __syncthreads();
            if (gr == 0) {
                const ULL* rd = &Red[(w * 32 + tc) * 4];
                const ULL ONE = pack2(1.0f);
                ulonglong2 v0 = *(const ulonglong2*)&rd[0];
                ulonglong2 v1 = *(const ulonglong2*)&rd[2];
                o[0][0] = ffma2(ONE, v0.x, o[0][0]);
                o[0][1] = ffma2(ONE, v0.y, o[0][1]);
                o[1][0] = ffma2(ONE, v1.x, o[1][0]);
                o[1][1] = ffma2(ONE, v1.y, o[1][1]);
            }

            // ---------------- RK4 epilogue (packed, warps 0-15) -------------
            if (epi_w) {
                if (s == 0) {
                    #pragma unroll
                    for (int p = 0; p < 2; p++) { acc[p][0] = o[p][0]; acc[p][1] = o[p][1]; }
                } else {
                    ULL cwv = pack2((s == 3) ? 1.0f : 2.0f);
                    #pragma unroll
                    for (int p = 0; p < 2; p++) {
                        acc[p][0] = ffma2(cwv, o[p][0], acc[p][0]);
                        acc[p][1] = ffma2(cwv, o[p][1], acc[p][1]);
                    }
                }
                if (s < 3) {
                    ULL ewv = pack2((s < 2) ? half : dt);
                    #pragma unroll
                    for (int p = 0; p < 2; p++) {
                        ulonglong2 yy;
                        yy.x = ffma2(ewv, o[p][0], yb[p][0]);
                        yy.y = ffma2(ewv, o[p][1], yb[p][1]);
                        *(ulonglong2*)&Yp[(2 * rga + p) * LATENTS + cb] = yy;
                    }
                } else {
                    ULL c6 = pack2(dt * (1.0f / 6.0f));
                    #pragma unroll
                    for (int p = 0; p < 2; p++) {
                        yb[p][0] = ffma2(c6, acc[p][0], yb[p][0]);
                        yb[p][1] = ffma2(c6, acc[p][1], yb[p][1]);
                        ulonglong2 yy; yy.x = yb[p][0]; yy.y = yb[p][1];
                        *(ulonglong2*)&Yp[(2 * rga + p) * LATENTS + cb] = yy;
                        int r = row0 + 4 * rga + 2 * p;
                        float lo, hi;
                        size_t base0 = ((size_t)r * TSTEPS + (t + 1)) * LATENTS + cb;
                        size_t base1 = ((size_t)(r + 1) * TSTEPS + (t + 1)) * LATENTS + cb;
                        unpack2(yb[p][0], lo, hi);
                        out[base0] = lo;     out[base1] = hi;
                        unpack2(yb[p][1], lo, hi);
                        out[base0 + 1] = lo; out[base1 + 1] = hi;
                    }
                }
            }
            __syncthreads();
        }
    }
}

extern "C" void kernel_launch(void* const* d_in, const int* in_sizes, int n_in,
                              void* d_out, int out_size) {
    const float* fp = (const float*)d_in[0];
    const float* ts = (const float*)d_in[1];
    const float* W1 = (const float*)d_in[2];
    const float* b1 = (const float*)d_in[3];
    const float* W2 = (const float*)d_in[4];
    const float* b2 = (const float*)d_in[5];
    float* out = (float*)d_out;

    cudaFuncSetAttribute(ode_rk4_kernel,
                         cudaFuncAttributeMaxDynamicSharedMemorySize, SM_BYTES);
    ode_rk4_kernel<<<NROWS / TM, NTHR, SM_BYTES>>>(fp, ts, W1, b1, W2, b2, out);
}

// round 15
// speedup vs baseline: 1.2497x; 1.2497x over previous
#include <cuda_runtime.h>

#define LATENTS 128
#define HIDDEN  256
#define TM      32
#define NTHR    1024
#define TSTEPS  100
#define NROWS   4096

typedef unsigned long long ULL;

__device__ __forceinline__ ULL ffma2(ULL a, ULL b, ULL c) {
    ULL d; asm("fma.rn.f32x2 %0, %1, %2, %3;" : "=l"(d) : "l"(a), "l"(b), "l"(c)); return d;
}
__device__ __forceinline__ ULL add2(ULL a, ULL b) {
    ULL d; asm("add.rn.f32x2 %0, %1, %2;" : "=l"(d) : "l"(a), "l"(b)); return d;
}
__device__ __forceinline__ ULL pack2(float x) {
    ULL d; asm("mov.b64 %0, {%1, %1};" : "=l"(d) : "f"(x)); return d;
}
__device__ __forceinline__ ULL packab(float a, float b) {
    ULL d; asm("mov.b64 %0, {%1, %2};" : "=l"(d) : "f"(a), "f"(b)); return d;
}
__device__ __forceinline__ void unpack2(ULL v, float& lo, float& hi) {
    asm("mov.b64 {%0, %1}, %2;" : "=f"(lo), "=f"(hi) : "l"(v));
}
__device__ __forceinline__ float fast_tanh(float x) {
    float e = __expf(2.0f * x);
    return 1.0f - __fdividef(2.0f, e + 1.0f);
}

// smem (bytes): W1s [0,131072)       fp32[128][256]
//               Yp  [131072,147456)  ULL [16][128]   row-pair state
//               Zp  [147456,180224)  ULL [16][256]   row-pair tanh acts
//               Red [180224,212992)  32KB: G1 h-partials / G2 o-partials+finals
#define SM_BYTES 212992

__global__ __launch_bounds__(NTHR, 1)
void ode_rk4_kernel(const float* __restrict__ fp,
                    const float* __restrict__ ts,
                    const float* __restrict__ W1,
                    const float* __restrict__ b1,
                    const float* __restrict__ W2,
                    const float* __restrict__ b2,
                    float* __restrict__ out)
{
    extern __shared__ char smraw[];
    float* W1s = (float*)smraw;
    ULL*   Yp  = (ULL*)(smraw + 131072);
    ULL*   Zp  = (ULL*)(smraw + 147456);
    ULL*   Red = (ULL*)(smraw + 180224);

    const int tid = threadIdx.x;
    const int tc  = tid & 31;
    const int w   = tid >> 5;            // 0..31
    // GEMM1: R12 tiling x 2 k-halves
    const int kg1 = w >> 4;              // k-half: ks [64*kg1, 64*kg1+64)
    const int w15 = w & 15;
    const int wr  = w15 >> 2;            // row group: pairs 4wr..4wr+3
    const int wc  = w15 & 3;             // col block: 64wc
    const int c1  = 64 * wc + 2 * tc;
    // GEMM2 (w<16): exact R12 mapping
    const int rg  = (w & 7) >> 1;        // pairs 4rg..4rg+3
    const int wc2 = w & 1;
    const int cb  = 64 * wc2 + 2 * tc;
    const int gr  = (w >> 3) & 1;        // k-half for G2
    const bool g2w = (w < 16);
    const int pe0 = 4 * rg + 2 * gr;     // this warp's 2 epilogue pairs
    const int row0 = blockIdx.x * TM;

    // Stage W1 (coalesced float4).
    for (int i = tid; i < LATENTS * HIDDEN / 4; i += NTHR)
        ((float4*)W1s)[i] = ((const float4*)W1)[i];

    // t=0 output, fully coalesced.
    for (int i = tid; i < TM * LATENTS / 4; i += NTHR) {
        int r = i >> 5, c4 = i & 31;
        float4 v = ((const float4*)(fp + (size_t)(row0 + r) * LATENTS))[c4];
        ((float4*)(out + (size_t)(row0 + r) * TSTEPS * LATENTS))[c4] = v;
    }

    const ULL rb1lo = pack2(b1[c1]);
    const ULL rb1hi = pack2(b1[c1 + 1]);

    ULL yb[2][2], acc[2][2], rb2[2];
    rb2[0] = pack2(b2[cb]);
    rb2[1] = pack2(b2[cb + 1]);
    if (g2w) {
        #pragma unroll
        for (int p = 0; p < 2; p++) {
            int r = row0 + 2 * (pe0 + p);
            yb[p][0] = packab(fp[(size_t)r * LATENTS + cb],     fp[(size_t)(r + 1) * LATENTS + cb]);
            yb[p][1] = packab(fp[(size_t)r * LATENTS + cb + 1], fp[(size_t)(r + 1) * LATENTS + cb + 1]);
            ulonglong2 yy; yy.x = yb[p][0]; yy.y = yb[p][1];
            *(ulonglong2*)&Yp[(pe0 + p) * LATENTS + cb] = yy;
        }
    }
    __syncthreads();

    for (int t = 0; t < TSTEPS - 1; t++) {
        float dt   = __ldg(&ts[t + 1]) - __ldg(&ts[t]);
        float half = 0.5f * dt;

        #pragma unroll 1
        for (int s = 0; s < 4; s++) {
            // ------- GEMM1: 32 warps, k-split halves of [0,128) ------------
            ULL h[4][2];
            if (kg1 == 0) {
                #pragma unroll
                for (int p = 0; p < 4; p++) { h[p][0] = rb1lo; h[p][1] = rb1hi; }
            } else {
                #pragma unroll
                for (int p = 0; p < 4; p++) { h[p][0] = 0ULL; h[p][1] = 0ULL; }
            }
            {
                const int kofs = 64 * kg1;
                const float* w1c = &W1s[c1];
                const ULL*   yp0 = &Yp[(4 * wr + 0) * LATENTS];
                const ULL*   yp1 = &Yp[(4 * wr + 1) * LATENTS];
                const ULL*   yp2 = &Yp[(4 * wr + 2) * LATENTS];
                const ULL*   yp3 = &Yp[(4 * wr + 3) * LATENTS];
                #pragma unroll 2
                for (int k0 = kofs; k0 < kofs + 64; k0 += 2) {
                    ulonglong2 a0 = *(const ulonglong2*)&yp0[k0];
                    ulonglong2 a1 = *(const ulonglong2*)&yp1[k0];
                    ulonglong2 a2 = *(const ulonglong2*)&yp2[k0];
                    ulonglong2 a3 = *(const ulonglong2*)&yp3[k0];
                    ULL wv0 = *(const ULL*)&w1c[(k0    ) * HIDDEN];
                    ULL wv1 = *(const ULL*)&w1c[(k0 + 1) * HIDDEN];
                    float wl, wh;
                    unpack2(wv0, wl, wh);
                    { ULL bl = pack2(wl), bh = pack2(wh);
                      h[0][0] = ffma2(a0.x, bl, h[0][0]); h[0][1] = ffma2(a0.x, bh, h[0][1]);
                      h[1][0] = ffma2(a1.x, bl, h[1][0]); h[1][1] = ffma2(a1.x, bh, h[1][1]);
                      h[2][0] = ffma2(a2.x, bl, h[2][0]); h[2][1] = ffma2(a2.x, bh, h[2][1]);
                      h[3][0] = ffma2(a3.x, bl, h[3][0]); h[3][1] = ffma2(a3.x, bh, h[3][1]); }
                    unpack2(wv1, wl, wh);
                    { ULL bl = pack2(wl), bh = pack2(wh);
                      h[0][0] = ffma2(a0.y, bl, h[0][0]); h[0][1] = ffma2(a0.y, bh, h[0][1]);
                      h[1][0] = ffma2(a1.y, bl, h[1][0]); h[1][1] = ffma2(a1.y, bh, h[1][1]);
                      h[2][0] = ffma2(a2.y, bl, h[2][0]); h[2][1] = ffma2(a2.y, bh, h[2][1]);
                      h[3][0] = ffma2(a3.y, bl, h[3][0]); h[3][1] = ffma2(a3.y, bh, h[3][1]); }
                }
            }

            // G2 warps: hoist first W2 prefetch (lands during tanh window).
            ULL wbuf[2][8];
            const float* Wg = W2 + (size_t)(128 * gr) * LATENTS + cb;
            if (g2w) {
                #pragma unroll
                for (int q = 0; q < 8; q++)
                    wbuf[0][q] = *(const ULL*)&Wg[q * LATENTS];
            }

            // publish upper-half h partials
            if (kg1 == 1) {
                ULL* rd = &Red[((w - 16) * 32 + tc) * 8];
                #pragma unroll
                for (int p = 0; p < 4; p++) {
                    ulonglong2 v; v.x = h[p][0]; v.y = h[p][1];
                    *(ulonglong2*)&rd[2 * p] = v;
                }
            }
            __syncthreads();                                   // barA

            if (kg1 == 0) {
                const ULL* rd = &Red[(w * 32 + tc) * 8];
                #pragma unroll
                for (int p = 0; p < 4; p++) {
                    ulonglong2 v = *(const ulonglong2*)&rd[2 * p];
                    h[p][0] = add2(h[p][0], v.x);
                    h[p][1] = add2(h[p][1], v.y);
                }
                // tanh -> Zp (dense STS.128, conflict-free).
                #pragma unroll
                for (int p = 0; p < 4; p++) {
                    float x0, x1, x2, x3;
                    unpack2(h[p][0], x0, x1);
                    unpack2(h[p][1], x2, x3);
                    ulonglong2 zz;
                    zz.x = packab(fast_tanh(x0), fast_tanh(x1));
                    zz.y = packab(fast_tanh(x2), fast_tanh(x3));
                    *(ulonglong2*)&Zp[(4 * wr + p) * HIDDEN + c1] = zz;
                }
            }
            __syncthreads();                                   // barB

            // ------- GEMM2 (w<16, exact R12): W2 streamed via LDG -----------
            ULL o[4][2];
            if (gr == 0) {
                #pragma unroll
                for (int p = 0; p < 4; p++) { o[p][0] = rb2[0]; o[p][1] = rb2[1]; }
            } else {
                #pragma unroll
                for (int p = 0; p < 4; p++) { o[p][0] = 0ULL; o[p][1] = 0ULL; }
            }

            if (g2w) {
                const ULL* zb0 = &Zp[(4 * rg + 0) * HIDDEN + 128 * gr];
                const ULL* zb1 = &Zp[(4 * rg + 1) * HIDDEN + 128 * gr];
                const ULL* zb2 = &Zp[(4 * rg + 2) * HIDDEN + 128 * gr];
                const ULL* zb3 = &Zp[(4 * rg + 3) * HIDDEN + 128 * gr];
                #pragma unroll 1
                for (int c = 0; c < 16; c++) {
                    if (c < 15) {
                        #pragma unroll
                        for (int q = 0; q < 8; q++)
                            wbuf[(c + 1) & 1][q] = *(const ULL*)&Wg[(8 * (c + 1) + q) * LATENTS];
                    }
                    #pragma unroll
                    for (int q = 0; q < 8; q += 2) {
                        const int kk = 8 * c + q;
                        ulonglong2 a0 = *(const ulonglong2*)&zb0[kk];
                        ulonglong2 a1 = *(const ulonglong2*)&zb1[kk];
                        ulonglong2 a2 = *(const ulonglong2*)&zb2[kk];
                        ulonglong2 a3 = *(const ulonglong2*)&zb3[kk];
                        ULL wv0 = wbuf[c & 1][q];
                        ULL wv1 = wbuf[c & 1][q + 1];
                        float wl, wh;
                        unpack2(wv0, wl, wh);
                        { ULL bl = pack2(wl), bh = pack2(wh);
                          o[0][0] = ffma2(a0.x, bl, o[0][0]); o[0][1] = ffma2(a0.x, bh, o[0][1]);
                          o[1][0] = ffma2(a1.x, bl, o[1][0]); o[1][1] = ffma2(a1.x, bh, o[1][1]);
                          o[2][0] = ffma2(a2.x, bl, o[2][0]); o[2][1] = ffma2(a2.x, bh, o[2][1]);
                          o[3][0] = ffma2(a3.x, bl, o[3][0]); o[3][1] = ffma2(a3.x, bh, o[3][1]); }
                        unpack2(wv1, wl, wh);
                        { ULL bl = pack2(wl), bh = pack2(wh);
                          o[0][0] = ffma2(a0.y, bl, o[0][0]); o[0][1] = ffma2(a0.y, bh, o[0][1]);
                          o[1][0] = ffma2(a1.y, bl, o[1][0]); o[1][1] = ffma2(a1.y, bh, o[1][1]);
                          o[2][0] = ffma2(a2.y, bl, o[2][0]); o[2][1] = ffma2(a2.y, bh, o[2][1]);
                          o[3][0] = ffma2(a3.y, bl, o[3][0]); o[3][1] = ffma2(a3.y, bh, o[3][1]); }
                    }
                }
            }

            // gr=1 publishes o partials
            if (g2w && gr == 1) {
                ULL* rd = &Red[((w - 8) * 32 + tc) * 8];
                #pragma unroll
                for (int p = 0; p < 4; p++) {
                    ulonglong2 v; v.x = o[p][0]; v.y = o[p][1];
                    *(ulonglong2*)&rd[2 * p] = v;
                }
            }
            __syncthreads();                                   // barC

            // gr=0 sums and publishes finals (into the slots it just read)
            if (g2w && gr == 0) {
                ULL* rd = &Red[(w * 32 + tc) * 8];
                #pragma unroll
                for (int p = 0; p < 4; p++) {
                    ulonglong2 v = *(const ulonglong2*)&rd[2 * p];
                    o[p][0] = add2(o[p][0], v.x);
                    o[p][1] = add2(o[p][1], v.y);
                    ulonglong2 f; f.x = o[p][0]; f.y = o[p][1];
                    *(ulonglong2*)&rd[2 * p] = f;
                }
            }
            __syncthreads();                                   // barD

            // ------- RK4 epilogue: 16 warps, 2 pairs each -------------------
            if (g2w) {
                ULL oe[2][2];
                if (gr == 0) {
                    oe[0][0] = o[0][0]; oe[0][1] = o[0][1];
                    oe[1][0] = o[1][0]; oe[1][1] = o[1][1];
                } else {
                    const ULL* rd = &Red[((w - 8) * 32 + tc) * 8];
                    ulonglong2 a = *(const ulonglong2*)&rd[4];
                    ulonglong2 b = *(const ulonglong2*)&rd[6];
                    oe[0][0] = a.x; oe[0][1] = a.y;
                    oe[1][0] = b.x; oe[1][1] = b.y;
                }
                if (s == 0) {
                    #pragma unroll
                    for (int p = 0; p < 2; p++) { acc[p][0] = oe[p][0]; acc[p][1] = oe[p][1]; }
                } else {
                    ULL cwv = pack2((s == 3) ? 1.0f : 2.0f);
                    #pragma unroll
                    for (int p = 0; p < 2; p++) {
                        acc[p][0] = ffma2(cwv, oe[p][0], acc[p][0]);
                        acc[p][1] = ffma2(cwv, oe[p][1], acc[p][1]);
                    }
                }
                if (s < 3) {
                    ULL ewv = pack2((s < 2) ? half : dt);
                    #pragma unroll
                    for (int p = 0; p < 2; p++) {
                        ulonglong2 yy;
                        yy.x = ffma2(ewv, oe[p][0], yb[p][0]);
                        yy.y = ffma2(ewv, oe[p][1], yb[p][1]);
                        *(ulonglong2*)&Yp[(pe0 + p) * LATENTS + cb] = yy;
                    }
                } else {
                    ULL c6 = pack2(dt * (1.0f / 6.0f));
                    #pragma unroll
                    for (int p = 0; p < 2; p++) {
                        yb[p][0] = ffma2(c6, acc[p][0], yb[p][0]);
                        yb[p][1] = ffma2(c6, acc[p][1], yb[p][1]);
                        ulonglong2 yy; yy.x = yb[p][0]; yy.y = yb[p][1];
                        *(ulonglong2*)&Yp[(pe0 + p) * LATENTS + cb] = yy;
                        int r = row0 + 2 * (pe0 + p);
                        float lo, hi;
                        size_t base0 = ((size_t)r * TSTEPS + (t + 1)) * LATENTS + cb;
                        size_t base1 = ((size_t)(r + 1) * TSTEPS + (t + 1)) * LATENTS + cb;
                        unpack2(yb[p][0], lo, hi);
                        out[base0] = lo;     out[base1] = hi;
                        unpack2(yb[p][1], lo, hi);
                        out[base0 + 1] = lo; out[base1 + 1] = hi;
                    }
                }
            }
            __syncthreads();                                   // barE
        }
    }
}

extern "C" void kernel_launch(void* const* d_in, const int* in_sizes, int n_in,
                              void* d_out, int out_size) {
    const float* fp = (const float*)d_in[0];
    const float* ts = (const float*)d_in[1];
    const float* W1 = (const float*)d_in[2];
    const float* b1 = (const float*)d_in[3];
    const float* W2 = (const float*)d_in[4];
    const float* b2 = (const float*)d_in[5];
    float* out = (float*)d_out;

    cudaFuncSetAttribute(ode_rk4_kernel,
                         cudaFuncAttributeMaxDynamicSharedMemorySize, SM_BYTES);
    ode_rk4_kernel<<<NROWS / TM, NTHR, SM_BYTES>>>(fp, ts, W1, b1, W2, b2, out);
}

// round 16
// speedup vs baseline: 2.4475x; 1.9585x over previous
#include <cuda_runtime.h>

#define LATENTS 128
#define HIDDEN  256
#define TM      32
#define NTHR    512
#define TSTEPS  100
#define NROWS   4096

typedef unsigned long long ULL;

__device__ __forceinline__ ULL ffma2(ULL a, ULL b, ULL c) {
    ULL d; asm("fma.rn.f32x2 %0, %1, %2, %3;" : "=l"(d) : "l"(a), "l"(b), "l"(c)); return d;
}
__device__ __forceinline__ ULL pack2(float x) {
    ULL d; asm("mov.b64 %0, {%1, %1};" : "=l"(d) : "f"(x)); return d;
}
__device__ __forceinline__ ULL packab(float a, float b) {
    ULL d; asm("mov.b64 %0, {%1, %2};" : "=l"(d) : "f"(a), "f"(b)); return d;
}
__device__ __forceinline__ void unpack2(ULL v, float& lo, float& hi) {
    asm("mov.b64 {%0, %1}, %2;" : "=f"(lo), "=f"(hi) : "l"(v));
}
__device__ __forceinline__ float fast_tanh(float x) {
    float e = __expf(2.0f * x);
    return 1.0f - __fdividef(2.0f, e + 1.0f);
}

// smem (bytes): W1s [0,131072)       fp32[128][256]
//               Yp  [131072,147456)  ULL [16][128]   row-pair state
//               Zp  [147456,180224)  ULL [16][256]   row-pair tanh acts
//               Red [180224,196608)  16KB partner-reduction buffer
#define SM_BYTES 196608

__global__ __launch_bounds__(NTHR, 1)
void ode_rk4_kernel(const float* __restrict__ fp,
                    const float* __restrict__ ts,
                    const float* __restrict__ W1,
                    const float* __restrict__ b1,
                    const float* __restrict__ W2,
                    const float* __restrict__ b2,
                    float* __restrict__ out)
{
    extern __shared__ char smraw[];
    float* W1s = (float*)smraw;
    ULL*   Yp  = (ULL*)(smraw + 131072);
    ULL*   Zp  = (ULL*)(smraw + 147456);
    ULL*   Red = (ULL*)(smraw + 180224);

    const int tid = threadIdx.x;
    const int tc  = tid & 31;
    const int w   = tid >> 5;
    const int wr  = w >> 2;          // GEMM1 row group: pairs 4wr..4wr+3
    const int wc  = w & 3;           // GEMM1 col block: 64wc
    const int rg  = (w & 7) >> 1;    // GEMM2 row tile: pairs 4rg..4rg+3
    const int wc2 = w & 1;           // GEMM2 col block: 64wc2
    const int gr  = w >> 3;          // GEMM2 k-half: ks [128gr, 128gr+128)
    const bool epi_w = (w < 8);
    const int row0 = blockIdx.x * TM;

    // Stage W1 (coalesced float4).
    for (int i = tid; i < LATENTS * HIDDEN / 4; i += NTHR)
        ((float4*)W1s)[i] = ((const float4*)W1)[i];

    // t=0 output, fully coalesced.
    for (int i = tid; i < TM * LATENTS / 4; i += NTHR) {
        int r = i >> 5, c4 = i & 31;
        float4 v = ((const float4*)(fp + (size_t)(row0 + r) * LATENTS))[c4];
        ((float4*)(out + (size_t)(row0 + r) * TSTEPS * LATENTS))[c4] = v;
    }

    const ULL rb1lo = pack2(b1[64 * wc + 2 * tc]);
    const ULL rb1hi = pack2(b1[64 * wc + 2 * tc + 1]);

    ULL yb[4][2], acc[4][2], rb2[2];
    const int cb = 64 * wc2 + 2 * tc;
    rb2[0] = pack2(b2[cb]);
    rb2[1] = pack2(b2[cb + 1]);
    if (epi_w) {
        #pragma unroll
        for (int p = 0; p < 4; p++) {
            int r = row0 + 8 * rg + 2 * p;
            yb[p][0] = packab(fp[(size_t)r * LATENTS + cb],     fp[(size_t)(r + 1) * LATENTS + cb]);
            yb[p][1] = packab(fp[(size_t)r * LATENTS + cb + 1], fp[(size_t)(r + 1) * LATENTS + cb + 1]);
            ulonglong2 yy; yy.x = yb[p][0]; yy.y = yb[p][1];
            *(ulonglong2*)&Yp[(4 * rg + p) * LATENTS + cb] = yy;
        }
    }
    __syncthreads();

    const float* Wg = W2 + (size_t)(128 * gr) * LATENTS + cb;

    for (int t = 0; t < TSTEPS - 1; t++) {
        float dt   = __ldg(&ts[t + 1]) - __ldg(&ts[t]);
        float half = 0.5f * dt;

        #pragma unroll 1
        for (int s = 0; s < 4; s++) {
            // ---------------- GEMM1 (all 16 warps, row-pair) ----------------
            ULL h[4][2];
            #pragma unroll
            for (int p = 0; p < 4; p++) { h[p][0] = rb1lo; h[p][1] = rb1hi; }
            {
                const float* w1c = &W1s[64 * wc + 2 * tc];
                const ULL*   yp0 = &Yp[(4 * wr + 0) * LATENTS];
                const ULL*   yp1 = &Yp[(4 * wr + 1) * LATENTS];
                const ULL*   yp2 = &Yp[(4 * wr + 2) * LATENTS];
                const ULL*   yp3 = &Yp[(4 * wr + 3) * LATENTS];
                #pragma unroll 2
                for (int k0 = 0; k0 < LATENTS; k0 += 2) {
                    ulonglong2 a0 = *(const ulonglong2*)&yp0[k0];
                    ulonglong2 a1 = *(const ulonglong2*)&yp1[k0];
                    ulonglong2 a2 = *(const ulonglong2*)&yp2[k0];
                    ulonglong2 a3 = *(const ulonglong2*)&yp3[k0];
                    ULL wv0 = *(const ULL*)&w1c[(k0    ) * HIDDEN];
                    ULL wv1 = *(const ULL*)&w1c[(k0 + 1) * HIDDEN];
                    float wl, wh;
                    unpack2(wv0, wl, wh);
                    { ULL bl = pack2(wl), bh = pack2(wh);
                      h[0][0] = ffma2(a0.x, bl, h[0][0]); h[0][1] = ffma2(a0.x, bh, h[0][1]);
                      h[1][0] = ffma2(a1.x, bl, h[1][0]); h[1][1] = ffma2(a1.x, bh, h[1][1]);
                      h[2][0] = ffma2(a2.x, bl, h[2][0]); h[2][1] = ffma2(a2.x, bh, h[2][1]);
                      h[3][0] = ffma2(a3.x, bl, h[3][0]); h[3][1] = ffma2(a3.x, bh, h[3][1]); }
                    unpack2(wv1, wl, wh);
                    { ULL bl = pack2(wl), bh = pack2(wh);
                      h[0][0] = ffma2(a0.y, bl, h[0][0]); h[0][1] = ffma2(a0.y, bh, h[0][1]);
                      h[1][0] = ffma2(a1.y, bl, h[1][0]); h[1][1] = ffma2(a1.y, bh, h[1][1]);
                      h[2][0] = ffma2(a2.y, bl, h[2][0]); h[2][1] = ffma2(a2.y, bh, h[2][1]);
                      h[3][0] = ffma2(a3.y, bl, h[3][0]); h[3][1] = ffma2(a3.y, bh, h[3][1]); }
                }
            }

            // tanh -> Zp (dense STS.128, conflict-free).
            #pragma unroll
            for (int p = 0; p < 4; p++) {
                float x0, x1, x2, x3;
                unpack2(h[p][0], x0, x1);
                unpack2(h[p][1], x2, x3);
                ulonglong2 zz;
                zz.x = packab(fast_tanh(x0), fast_tanh(x1));
                zz.y = packab(fast_tanh(x2), fast_tanh(x3));
                *(ulonglong2*)&Zp[(4 * wr + p) * HIDDEN + 64 * wc + 2 * tc] = zz;
            }

            // Hoisted W2 first-chunk prefetch: LDGs fly during the barrier.
            ULL wbuf[2][8];
            #pragma unroll
            for (int q = 0; q < 8; q++)
                wbuf[0][q] = *(const ULL*)&Wg[q * LATENTS];

            __syncthreads();

            // ------- GEMM2: all 16 warps; W2 streamed via LDG (L2-resident) -
            ULL o[4][2];
            if (gr == 0) {
                #pragma unroll
                for (int p = 0; p < 4; p++) { o[p][0] = rb2[0]; o[p][1] = rb2[1]; }
            } else {
                #pragma unroll
                for (int p = 0; p < 4; p++) { o[p][0] = 0ULL; o[p][1] = 0ULL; }
            }

            {
                const ULL* zb0 = &Zp[(4 * rg + 0) * HIDDEN + 128 * gr];
                const ULL* zb1 = &Zp[(4 * rg + 1) * HIDDEN + 128 * gr];
                const ULL* zb2 = &Zp[(4 * rg + 2) * HIDDEN + 128 * gr];
                const ULL* zb3 = &Zp[(4 * rg + 3) * HIDDEN + 128 * gr];

                #pragma unroll 2
                for (int c = 0; c < 16; c++) {
                    if (c < 15) {
                        #pragma unroll
                        for (int q = 0; q < 8; q++)
                            wbuf[(c + 1) & 1][q] = *(const ULL*)&Wg[(8 * (c + 1) + q) * LATENTS];
                    }
                    #pragma unroll
                    for (int q = 0; q < 8; q += 2) {
                        const int kk = 8 * c + q;
                        ulonglong2 a0 = *(const ulonglong2*)&zb0[kk];
                        ulonglong2 a1 = *(const ulonglong2*)&zb1[kk];
                        ulonglong2 a2 = *(const ulonglong2*)&zb2[kk];
                        ulonglong2 a3 = *(const ulonglong2*)&zb3[kk];
                        ULL wv0 = wbuf[c & 1][q];
                        ULL wv1 = wbuf[c & 1][q + 1];
                        float wl, wh;
                        unpack2(wv0, wl, wh);
                        { ULL bl = pack2(wl), bh = pack2(wh);
                          o[0][0] = ffma2(a0.x, bl, o[0][0]); o[0][1] = ffma2(a0.x, bh, o[0][1]);
                          o[1][0] = ffma2(a1.x, bl, o[1][0]); o[1][1] = ffma2(a1.x, bh, o[1][1]);
                          o[2][0] = ffma2(a2.x, bl, o[2][0]); o[2][1] = ffma2(a2.x, bh, o[2][1]);
                          o[3][0] = ffma2(a3.x, bl, o[3][0]); o[3][1] = ffma2(a3.x, bh, o[3][1]); }
                        unpack2(wv1, wl, wh);
                        { ULL bl = pack2(wl), bh = pack2(wh);
                          o[0][0] = ffma2(a0.y, bl, o[0][0]); o[0][1] = ffma2(a0.y, bh, o[0][1]);
                          o[1][0] = ffma2(a1.y, bl, o[1][0]); o[1][1] = ffma2(a1.y, bh, o[1][1]);
                          o[2][0] = ffma2(a2.y, bl, o[2][0]); o[2][1] = ffma2(a2.y, bh, o[2][1]);
                          o[3][0] = ffma2(a3.y, bl, o[3][0]); o[3][1] = ffma2(a3.y, bh, o[3][1]); }
                    }
                }
            }

            // ------- partner reduction: group1 -> Red, group0 adds ----------
            if (gr == 1) {
                ULL* rd = &Red[((w - 8) * 32 + tc) * 8];
                #pragma unroll
                for (int p = 0; p < 4; p++) {
                    ulonglong2 v; v.x = o[p][0]; v.y = o[p][1];
                    *(ulonglong2*)&rd[2 * p] = v;
                }
            }
            __syncthreads();
            if (gr == 0) {
                const ULL* rd = &Red[(w * 32 + tc) * 8];
                const ULL ONE = pack2(1.0f);
                #pragma unroll
                for (int p = 0; p < 4; p++) {
                    ulonglong2 v = *(const ulonglong2*)&rd[2 * p];
                    o[p][0] = ffma2(ONE, v.x, o[p][0]);
                    o[p][1] = ffma2(ONE, v.y, o[p][1]);
                }
            }

            // ---------------- RK4 epilogue (packed, warps 0-7) --------------
            if (epi_w) {
                if (s == 0) {
                    #pragma unroll
                    for (int p = 0; p < 4; p++) { acc[p][0] = o[p][0]; acc[p][1] = o[p][1]; }
                } else {
                    ULL cwv = pack2((s == 3) ? 1.0f : 2.0f);
                    #pragma unroll
                    for (int p = 0; p < 4; p++) {
                        acc[p][0] = ffma2(cwv, o[p][0], acc[p][0]);
                        acc[p][1] = ffma2(cwv, o[p][1], acc[p][1]);
                    }
                }
                if (s < 3) {
                    ULL ewv = pack2((s < 2) ? half : dt);
                    #pragma unroll
                    for (int p = 0; p < 4; p++) {
                        ulonglong2 yy;
                        yy.x = ffma2(ewv, o[p][0], yb[p][0]);
                        yy.y = ffma2(ewv, o[p][1], yb[p][1]);
                        *(ulonglong2*)&Yp[(4 * rg + p) * LATENTS + cb] = yy;
                    }
                } else {
                    ULL c6 = pack2(dt * (1.0f / 6.0f));
                    #pragma unroll
                    for (int p = 0; p < 4; p++) {
                        yb[p][0] = ffma2(c6, acc[p][0], yb[p][0]);
                        yb[p][1] = ffma2(c6, acc[p][1], yb[p][1]);
                        ulonglong2 yy; yy.x = yb[p][0]; yy.y = yb[p][1];
                        *(ulonglong2*)&Yp[(4 * rg + p) * LATENTS + cb] = yy;
                        int r = row0 + 8 * rg + 2 * p;
                        float lo, hi;
                        size_t base0 = ((size_t)r * TSTEPS + (t + 1)) * LATENTS + cb;
                        size_t base1 = ((size_t)(r + 1) * TSTEPS + (t + 1)) * LATENTS + cb;
                        unpack2(yb[p][0], lo, hi);
                        out[base0] = lo;     out[base1] = hi;
                        unpack2(yb[p][1], lo, hi);
                        out[base0 + 1] = lo; out[base1 + 1] = hi;
                    }
                }
            }
            __syncthreads();
        }
    }
}

extern "C" void kernel_launch(void* const* d_in, const int* in_sizes, int n_in,
                              void* d_out, int out_size) {
    const float* fp = (const float*)d_in[0];
    const float* ts = (const float*)d_in[1];
    const float* W1 = (const float*)d_in[2];
    const float* b1 = (const float*)d_in[3];
    const float* W2 = (const float*)d_in[4];
    const float* b2 = (const float*)d_in[5];
    float* out = (float*)d_out;

    cudaFuncSetAttribute(ode_rk4_kernel,
                         cudaFuncAttributeMaxDynamicSharedMemorySize, SM_BYTES);
    ode_rk4_kernel<<<NROWS / TM, NTHR, SM_BYTES>>>(fp, ts, W1, b1, W2, b2, out);
}

// round 17
// speedup vs baseline: 2.4971x; 1.0203x over previous
#include <cuda_runtime.h>

#define LATENTS 128
#define HIDDEN  256
#define TM      32
#define NTHR    512
#define TSTEPS  100
#define NROWS   4096

typedef unsigned long long ULL;

__device__ __forceinline__ ULL ffma2(ULL a, ULL b, ULL c) {
    ULL d; asm("fma.rn.f32x2 %0, %1, %2, %3;" : "=l"(d) : "l"(a), "l"(b), "l"(c)); return d;
}
__device__ __forceinline__ ULL add2(ULL a, ULL b) {
    ULL d; asm("add.rn.f32x2 %0, %1, %2;" : "=l"(d) : "l"(a), "l"(b)); return d;
}
__device__ __forceinline__ ULL pack2(float x) {
    ULL d; asm("mov.b64 %0, {%1, %1};" : "=l"(d) : "f"(x)); return d;
}
__device__ __forceinline__ ULL packab(float a, float b) {
    ULL d; asm("mov.b64 %0, {%1, %2};" : "=l"(d) : "f"(a), "f"(b)); return d;
}
__device__ __forceinline__ void unpack2(ULL v, float& lo, float& hi) {
    asm("mov.b64 {%0, %1}, %2;" : "=f"(lo), "=f"(hi) : "l"(v));
}
__device__ __forceinline__ float fast_tanh(float x) {
    float e = __expf(2.0f * x);
    return 1.0f - __fdividef(2.0f, e + 1.0f);
}

// smem (bytes): W1s [0,131072)       fp32[128][256]
//               Yp  [131072,147456)  ULL [16][128]   row-pair state
//               Zp  [147456,180224)  ULL [16][256]   row-pair tanh acts
//               Red [180224,212992)  32KB: G1 h-partials / G2 o-partials
#define SM_BYTES 212992

__global__ __launch_bounds__(NTHR, 1)
void ode_rk4_kernel(const float* __restrict__ fp,
                    const float* __restrict__ ts,
                    const float* __restrict__ W1,
                    const float* __restrict__ b1,
                    const float* __restrict__ W2,
                    const float* __restrict__ b2,
                    float* __restrict__ out)
{
    extern __shared__ char smraw[];
    float* W1s = (float*)smraw;
    ULL*   Yp  = (ULL*)(smraw + 131072);
    ULL*   Zp  = (ULL*)(smraw + 147456);
    ULL*   Red = (ULL*)(smraw + 180224);

    const int tid = threadIdx.x;
    const int tc  = tid & 31;
    const int w   = tid >> 5;
    // GEMM1: 4 row-groups x 2 col-group-pairs x 2 k-halves
    const int kg  = w >> 3;          // k-half: ks [64kg, 64kg+64)
    const int w8  = w & 7;
    const int wr  = w8 >> 1;         // row group: pairs 4wr..4wr+3
    const int wc1g= w8 & 1;          // col blocks 64*wc1g and 64*wc1g+128
    const int c1a = 64 * wc1g + 2 * tc;
    const int c1b = c1a + 128;
    // GEMM2/epi (R12 mapping, unchanged)
    const int rg  = (w & 7) >> 1;
    const int wc2 = w & 1;
    const int cb  = 64 * wc2 + 2 * tc;
    const int gr  = w >> 3;
    const bool epi_w = (w < 8);
    const int row0 = blockIdx.x * TM;

    // Stage W1 (coalesced float4).
    for (int i = tid; i < LATENTS * HIDDEN / 4; i += NTHR)
        ((float4*)W1s)[i] = ((const float4*)W1)[i];

    // t=0 output, fully coalesced.
    for (int i = tid; i < TM * LATENTS / 4; i += NTHR) {
        int r = i >> 5, c4 = i & 31;
        float4 v = ((const float4*)(fp + (size_t)(row0 + r) * LATENTS))[c4];
        ((float4*)(out + (size_t)(row0 + r) * TSTEPS * LATENTS))[c4] = v;
    }

    ULL rb1[2][2];
    rb1[0][0] = pack2(b1[c1a]); rb1[0][1] = pack2(b1[c1a + 1]);
    rb1[1][0] = pack2(b1[c1b]); rb1[1][1] = pack2(b1[c1b + 1]);

    ULL yb[4][2], acc[4][2], rb2[2];
    rb2[0] = pack2(b2[cb]);
    rb2[1] = pack2(b2[cb + 1]);
    if (epi_w) {
        #pragma unroll
        for (int p = 0; p < 4; p++) {
            int r = row0 + 8 * rg + 2 * p;
            yb[p][0] = packab(fp[(size_t)r * LATENTS + cb],     fp[(size_t)(r + 1) * LATENTS + cb]);
            yb[p][1] = packab(fp[(size_t)r * LATENTS + cb + 1], fp[(size_t)(r + 1) * LATENTS + cb + 1]);
            ulonglong2 yy; yy.x = yb[p][0]; yy.y = yb[p][1];
            *(ulonglong2*)&Yp[(4 * rg + p) * LATENTS + cb] = yy;
        }
    }
    __syncthreads();

    const float* Wg = W2 + (size_t)(128 * gr) * LATENTS + cb;

    for (int t = 0; t < TSTEPS - 1; t++) {
        float dt   = __ldg(&ts[t + 1]) - __ldg(&ts[t]);
        float half = 0.5f * dt;

        #pragma unroll 1
        for (int s = 0; s < 4; s++) {
            // ------- GEMM1: 4 pairs x (2 col-blocks of 64) x k-half ---------
            ULL h[4][2][2];
            if (kg == 0) {
                #pragma unroll
                for (int p = 0; p < 4; p++)
                    #pragma unroll
                    for (int b = 0; b < 2; b++) {
                        h[p][b][0] = rb1[b][0]; h[p][b][1] = rb1[b][1];
                    }
            } else {
                #pragma unroll
                for (int p = 0; p < 4; p++)
                    #pragma unroll
                    for (int b = 0; b < 2; b++) { h[p][b][0] = 0ULL; h[p][b][1] = 0ULL; }
            }
            {
                const int kofs = 64 * kg;
                const float* wA = &W1s[c1a];
                const float* wB = &W1s[c1b];
                const ULL*   yp0 = &Yp[(4 * wr + 0) * LATENTS];
                const ULL*   yp1 = &Yp[(4 * wr + 1) * LATENTS];
                const ULL*   yp2 = &Yp[(4 * wr + 2) * LATENTS];
                const ULL*   yp3 = &Yp[(4 * wr + 3) * LATENTS];
                #pragma unroll 2
                for (int k0 = kofs; k0 < kofs + 64; k0 += 2) {
                    ulonglong2 a0 = *(const ulonglong2*)&yp0[k0];
                    ulonglong2 a1 = *(const ulonglong2*)&yp1[k0];
                    ulonglong2 a2 = *(const ulonglong2*)&yp2[k0];
                    ulonglong2 a3 = *(const ulonglong2*)&yp3[k0];
                    ULL wA0 = *(const ULL*)&wA[(k0    ) * HIDDEN];
                    ULL wA1 = *(const ULL*)&wA[(k0 + 1) * HIDDEN];
                    ULL wB0 = *(const ULL*)&wB[(k0    ) * HIDDEN];
                    ULL wB1 = *(const ULL*)&wB[(k0 + 1) * HIDDEN];
                    float wl, wh;
                    unpack2(wA0, wl, wh);
                    { ULL bl = pack2(wl), bh = pack2(wh);
                      h[0][0][0] = ffma2(a0.x, bl, h[0][0][0]); h[0][0][1] = ffma2(a0.x, bh, h[0][0][1]);
                      h[1][0][0] = ffma2(a1.x, bl, h[1][0][0]); h[1][0][1] = ffma2(a1.x, bh, h[1][0][1]);
                      h[2][0][0] = ffma2(a2.x, bl, h[2][0][0]); h[2][0][1] = ffma2(a2.x, bh, h[2][0][1]);
                      h[3][0][0] = ffma2(a3.x, bl, h[3][0][0]); h[3][0][1] = ffma2(a3.x, bh, h[3][0][1]); }
                    unpack2(wB0, wl, wh);
                    { ULL bl = pack2(wl), bh = pack2(wh);
                      h[0][1][0] = ffma2(a0.x, bl, h[0][1][0]); h[0][1][1] = ffma2(a0.x, bh, h[0][1][1]);
                      h[1][1][0] = ffma2(a1.x, bl, h[1][1][0]); h[1][1][1] = ffma2(a1.x, bh, h[1][1][1]);
                      h[2][1][0] = ffma2(a2.x, bl, h[2][1][0]); h[2][1][1] = ffma2(a2.x, bh, h[2][1][1]);
                      h[3][1][0] = ffma2(a3.x, bl, h[3][1][0]); h[3][1][1] = ffma2(a3.x, bh, h[3][1][1]); }
                    unpack2(wA1, wl, wh);
                    { ULL bl = pack2(wl), bh = pack2(wh);
                      h[0][0][0] = ffma2(a0.y, bl, h[0][0][0]); h[0][0][1] = ffma2(a0.y, bh, h[0][0][1]);
                      h[1][0][0] = ffma2(a1.y, bl, h[1][0][0]); h[1][0][1] = ffma2(a1.y, bh, h[1][0][1]);
                      h[2][0][0] = ffma2(a2.y, bl, h[2][0][0]); h[2][0][1] = ffma2(a2.y, bh, h[2][0][1]);
                      h[3][0][0] = ffma2(a3.y, bl, h[3][0][0]); h[3][0][1] = ffma2(a3.y, bh, h[3][0][1]); }
                    unpack2(wB1, wl, wh);
                    { ULL bl = pack2(wl), bh = pack2(wh);
                      h[0][1][0] = ffma2(a0.y, bl, h[0][1][0]); h[0][1][1] = ffma2(a0.y, bh, h[0][1][1]);
                      h[1][1][0] = ffma2(a1.y, bl, h[1][1][0]); h[1][1][1] = ffma2(a1.y, bh, h[1][1][1]);
                      h[2][1][0] = ffma2(a2.y, bl, h[2][1][0]); h[2][1][1] = ffma2(a2.y, bh, h[2][1][1]);
                      h[3][1][0] = ffma2(a3.y, bl, h[3][1][0]); h[3][1][1] = ffma2(a3.y, bh, h[3][1][1]); }
                }
            }

            // kg=1 publishes h partials (dense per-lane layout: 4 phases/store)
            if (kg == 1) {
                #pragma unroll
                for (int p = 0; p < 4; p++)
                    #pragma unroll
                    for (int b = 0; b < 2; b++) {
                        int j = p * 2 + b;
                        ulonglong2 v; v.x = h[p][b][0]; v.y = h[p][b][1];
                        *(ulonglong2*)&Red[w8 * 512 + j * 64 + tc * 2] = v;
                    }
            }
            __syncthreads();                                   // barA

            // kg=0: merge partials, tanh -> Zp (both col blocks)
            if (kg == 0) {
                #pragma unroll
                for (int p = 0; p < 4; p++)
                    #pragma unroll
                    for (int b = 0; b < 2; b++) {
                        int j = p * 2 + b;
                        ulonglong2 v = *(const ulonglong2*)&Red[w8 * 512 + j * 64 + tc * 2];
                        h[p][b][0] = add2(h[p][b][0], v.x);
                        h[p][b][1] = add2(h[p][b][1], v.y);
                    }
                #pragma unroll
                for (int p = 0; p < 4; p++) {
                    #pragma unroll
                    for (int b = 0; b < 2; b++) {
                        float x0, x1, x2, x3;
                        unpack2(h[p][b][0], x0, x1);
                        unpack2(h[p][b][1], x2, x3);
                        ulonglong2 zz;
                        zz.x = packab(fast_tanh(x0), fast_tanh(x1));
                        zz.y = packab(fast_tanh(x2), fast_tanh(x3));
                        int c = (b == 0) ? c1a : c1b;
                        *(ulonglong2*)&Zp[(4 * wr + p) * HIDDEN + c] = zz;
                    }
                }
            }
            __syncthreads();                                   // barB

            // ------- GEMM2 (exact R12): W2 streamed via LDG -----------------
            ULL o[4][2];
            if (gr == 0) {
                #pragma unroll
                for (int p = 0; p < 4; p++) { o[p][0] = rb2[0]; o[p][1] = rb2[1]; }
            } else {
                #pragma unroll
                for (int p = 0; p < 4; p++) { o[p][0] = 0ULL; o[p][1] = 0ULL; }
            }

            {
                const ULL* zb0 = &Zp[(4 * rg + 0) * HIDDEN + 128 * gr];
                const ULL* zb1 = &Zp[(4 * rg + 1) * HIDDEN + 128 * gr];
                const ULL* zb2 = &Zp[(4 * rg + 2) * HIDDEN + 128 * gr];
                const ULL* zb3 = &Zp[(4 * rg + 3) * HIDDEN + 128 * gr];

                ULL wbuf[2][8];
                #pragma unroll
                for (int q = 0; q < 8; q++)
                    wbuf[0][q] = *(const ULL*)&Wg[q * LATENTS];

                #pragma unroll 2
                for (int c = 0; c < 16; c++) {
                    if (c < 15) {
                        #pragma unroll
                        for (int q = 0; q < 8; q++)
                            wbuf[(c + 1) & 1][q] = *(const ULL*)&Wg[(8 * (c + 1) + q) * LATENTS];
                    }
                    #pragma unroll
                    for (int q = 0; q < 8; q += 2) {
                        const int kk = 8 * c + q;
                        ulonglong2 a0 = *(const ulonglong2*)&zb0[kk];
                        ulonglong2 a1 = *(const ulonglong2*)&zb1[kk];
                        ulonglong2 a2 = *(const ulonglong2*)&zb2[kk];
                        ulonglong2 a3 = *(const ulonglong2*)&zb3[kk];
                        ULL wv0 = wbuf[c & 1][q];
                        ULL wv1 = wbuf[c & 1][q + 1];
                        float wl, wh;
                        unpack2(wv0, wl, wh);
                        { ULL bl = pack2(wl), bh = pack2(wh);
                          o[0][0] = ffma2(a0.x, bl, o[0][0]); o[0][1] = ffma2(a0.x, bh, o[0][1]);
                          o[1][0] = ffma2(a1.x, bl, o[1][0]); o[1][1] = ffma2(a1.x, bh, o[1][1]);
                          o[2][0] = ffma2(a2.x, bl, o[2][0]); o[2][1] = ffma2(a2.x, bh, o[2][1]);
                          o[3][0] = ffma2(a3.x, bl, o[3][0]); o[3][1] = ffma2(a3.x, bh, o[3][1]); }
                        unpack2(wv1, wl, wh);
                        { ULL bl = pack2(wl), bh = pack2(wh);
                          o[0][0] = ffma2(a0.y, bl, o[0][0]); o[0][1] = ffma2(a0.y, bh, o[0][1]);
                          o[1][0] = ffma2(a1.y, bl, o[1][0]); o[1][1] = ffma2(a1.y, bh, o[1][1]);
                          o[2][0] = ffma2(a2.y, bl, o[2][0]); o[2][1] = ffma2(a2.y, bh, o[2][1]);
                          o[3][0] = ffma2(a3.y, bl, o[3][0]); o[3][1] = ffma2(a3.y, bh, o[3][1]); }
                    }
                }
            }

            // ------- partner reduction: group1 -> Red, group0 adds ----------
            if (gr == 1) {
                ULL* rd = &Red[((w - 8) * 32 + tc) * 8];
                #pragma unroll
                for (int p = 0; p < 4; p++) {
                    ulonglong2 v; v.x = o[p][0]; v.y = o[p][1];
                    *(ulonglong2*)&rd[2 * p] = v;
                }
            }
            __syncthreads();                                   // barC
            if (gr == 0) {
                const ULL* rd = &Red[(w * 32 + tc) * 8];
                const ULL ONE = pack2(1.0f);
                #pragma unroll
                for (int p = 0; p < 4; p++) {
                    ulonglong2 v = *(const ulonglong2*)&rd[2 * p];
                    o[p][0] = ffma2(ONE, v.x, o[p][0]);
                    o[p][1] = ffma2(ONE, v.y, o[p][1]);
                }
            }

            // ---------------- RK4 epilogue (packed, warps 0-7) --------------
            if (epi_w) {
                if (s == 0) {
                    #pragma unroll
                    for (int p = 0; p < 4; p++) { acc[p][0] = o[p][0]; acc[p][1] = o[p][1]; }
                } else {
                    ULL cwv = pack2((s == 3) ? 1.0f : 2.0f);
                    #pragma unroll
                    for (int p = 0; p < 4; p++) {
                        acc[p][0] = ffma2(cwv, o[p][0], acc[p][0]);
                        acc[p][1] = ffma2(cwv, o[p][1], acc[p][1]);
                    }
                }
                if (s < 3) {
                    ULL ewv = pack2((s < 2) ? half : dt);
                    #pragma unroll
                    for (int p = 0; p < 4; p++) {
                        ulonglong2 yy;
                        yy.x = ffma2(ewv, o[p][0], yb[p][0]);
                        yy.y = ffma2(ewv, o[p][1], yb[p][1]);
                        *(ulonglong2*)&Yp[(4 * rg + p) * LATENTS + cb] = yy;
                    }
                } else {
                    ULL c6 = pack2(dt * (1.0f / 6.0f));
                    #pragma unroll
                    for (int p = 0; p < 4; p++) {
                        yb[p][0] = ffma2(c6, acc[p][0], yb[p][0]);
                        yb[p][1] = ffma2(c6, acc[p][1], yb[p][1]);
                        ulonglong2 yy; yy.x = yb[p][0]; yy.y = yb[p][1];
                        *(ulonglong2*)&Yp[(4 * rg + p) * LATENTS + cb] = yy;
                        int r = row0 + 8 * rg + 2 * p;
                        float lo, hi;
                        size_t base0 = ((size_t)r * TSTEPS + (t + 1)) * LATENTS + cb;
                        size_t base1 = ((size_t)(r + 1) * TSTEPS + (t + 1)) * LATENTS + cb;
                        unpack2(yb[p][0], lo, hi);
                        out[base0] = lo;     out[base1] = hi;
                        unpack2(yb[p][1], lo, hi);
                        out[base0 + 1] = lo; out[base1 + 1] = hi;
                    }
                }
            }
            __syncthreads();                                   // barD
        }
    }
}

extern "C" void kernel_launch(void* const* d_in, const int* in_sizes, int n_in,
                              void* d_out, int out_size) {
    const float* fp = (const float*)d_in[0];
    const float* ts = (const float*)d_in[1];
    const float* W1 = (const float*)d_in[2];
    const float* b1 = (const float*)d_in[3];
    const float* W2 = (const float*)d_in[4];
    const float* b2 = (const float*)d_in[5];
    float* out = (float*)d_out;

    cudaFuncSetAttribute(ode_rk4_kernel,
                         cudaFuncAttributeMaxDynamicSharedMemorySize, SM_BYTES);
    ode_rk4_kernel<<<NROWS / TM, NTHR, SM_BYTES>>>(fp, ts, W1, b1, W2, b2, out);
}